// round 5
// baseline (speedup 1.0000x reference)
#include <cuda_runtime.h>
#include <cstdint>

#define N_IDX   4096
#define GRID_P  888          // 148 SMs * 6 CTAs
#define NITEMS  4096         // 2048 f1-quarters + 1024 f2 + 512 f3 + 512 f0
#define BUF_FLT 4224         // 33 rows * 128 cols (largest item)
#define BUF_B   16896
#define DYN_SMEM (2 * BUF_B + 16)

// Meta for f2/f3 (indexed by j). f1 uses compacted per-quarter buckets.
struct __align__(16) Meta { int p00; int d; float wy; float wx; };
__device__ Meta g_meta[3 * N_IDX];
__device__ int4 g_f1b[4 * N_IDX];   // f1 bucket entries: {p00, (j<<4)|(dyf<<1)|dxf, wy, wx}
__device__ int  g_cnt[4];

__global__ void zero_cnt() { if (threadIdx.x < 4) g_cnt[threadIdx.x] = 0; }

__global__ void precompute_meta(const int* __restrict__ indices) {
    int t = blockIdx.x * blockDim.x + threadIdx.x;
    if (t >= 3 * N_IDX) return;
    int lvl = t / N_IDX;        // 0 -> f1 (H=128), 1 -> f2 (64), 2 -> f3 (32)
    int j   = t - lvl * N_IDX;
    int H   = 128 >> lvl;
    float scale = (float)H * (1.0f / 256.0f);

    int idx = indices[j];
    int iy = idx >> 8;
    int ix = idx & 255;
    // half-pixel centers (align_corners=False)
    float sy = ((float)iy + 0.5f) * scale - 0.5f;
    float sx = ((float)ix + 0.5f) * scale - 0.5f;
    float y0f = floorf(sy), x0f = floorf(sx);
    float wy = sy - y0f,    wx = sx - x0f;
    int y0 = (int)y0f, x0 = (int)x0f;
    int y0c = min(max(y0,     0), H - 1);
    int y1c = min(max(y0 + 1, 0), H - 1);
    int x0c = min(max(x0,     0), H - 1);
    int x1c = min(max(x0 + 1, 0), H - 1);

    Meta m;
    m.p00 = y0c * H + x0c;
    m.d   = (((y1c - y0c) * H) << 16) | (x1c - x0c);
    m.wy  = wy;
    m.wx  = wx;
    g_meta[t] = m;

    if (lvl == 0) {
        int q = y0c >> 5;                       // quarter of the 128-row plane
        int pos = atomicAdd(&g_cnt[q], 1);
        int4 e;
        e.x = m.p00;
        e.y = (j << 4) | ((y1c - y0c) ? 2 : 0) | (x1c - x0c);
        e.z = __float_as_int(wy);
        e.w = __float_as_int(wx);
        g_f1b[q * N_IDX + pos] = e;
    }
}

__device__ __forceinline__ uint32_t smem_u32(const void* p) {
    uint32_t a;
    asm("{ .reg .u64 t; cvta.to.shared.u64 t, %1; cvt.u32.u64 %0, t; }"
        : "=r"(a) : "l"(p));
    return a;
}

__device__ __forceinline__ void wait_parity(uint32_t mbar, uint32_t phase) {
    asm volatile(
        "{\n\t.reg .pred P;\n\t"
        "W%=:\n\t"
        "mbarrier.try_wait.parity.acquire.cta.shared::cta.b64 P, [%0], %1, 0x989680;\n\t"
        "@!P bra W%=;\n\t}"
        :: "r"(mbar), "r"(phase) : "memory");
}

// tid==0 only: program mbarrier tx and kick the bulk copy for item `it`.
__device__ __forceinline__ void issue_copy(int it, uint32_t dst, uint32_t mbar,
                                           const float* f1, const float* f2,
                                           const float* f3) {
    const float* src = nullptr;
    int bytes = 0;
    if (it < 2048) {                       // f1 quarter-plane
        int plane = it >> 2, q = it & 3;
        src = f1 + (size_t)plane * 16384 + q * 4096;
        bytes = (q < 3 ? 33 : 32) * 512;   // 33 rows (32 for last) * 128 * 4B
    } else if (it < 3072) {                // f2 full plane (16KB)
        src = f2 + (size_t)(it - 2048) * 4096;
        bytes = 16384;
    } else if (it < 3584) {                // f3 4-channel group (16KB)
        src = f3 + (size_t)(it - 3072) * 4096;
        bytes = 16384;
    }                                      // else f0: no copy, tx=0
    asm volatile("mbarrier.arrive.expect_tx.shared.b64 _, [%0], %1;"
                 :: "r"(mbar), "r"(bytes) : "memory");
    if (bytes)
        asm volatile(
            "cp.async.bulk.shared::cta.global.mbarrier::complete_tx::bytes "
            "[%0], [%1], %2, [%3];"
            :: "r"(dst), "l"(src), "r"(bytes), "r"(mbar) : "memory");
}

__global__ __launch_bounds__(256) void persist_gather(
    const float* __restrict__ f0, const float* __restrict__ f1,
    const float* __restrict__ f2, const float* __restrict__ f3,
    const int*   __restrict__ indices, float* __restrict__ out)
{
    extern __shared__ float smem[];
    const int tid = threadIdx.x;
    uint64_t* mb = (uint64_t*)(smem + 2 * BUF_FLT);
    uint32_t mb_u32  = smem_u32(mb);
    uint32_t buf_u32 = smem_u32(smem);

    if (tid == 0) {
        asm volatile("mbarrier.init.shared.b64 [%0], 1;" :: "r"(mb_u32)     : "memory");
        asm volatile("mbarrier.init.shared.b64 [%0], 1;" :: "r"(mb_u32 + 8) : "memory");
    }
    __syncthreads();

    int k = 0;
    for (int it = blockIdx.x; it < NITEMS; it += GRID_P, k++) {
        if (tid == 0) {
            if (k == 0)
                issue_copy(it, buf_u32, mb_u32, f1, f2, f3);
            int nxt = it + GRID_P;
            if (nxt < NITEMS)
                issue_copy(nxt, buf_u32 + ((k + 1) & 1) * BUF_B,
                           mb_u32 + ((k + 1) & 1) * 8, f1, f2, f3);
        }
        wait_parity(mb_u32 + (k & 1) * 8, (k >> 1) & 1);
        const float* s = smem + (k & 1) * BUF_FLT;

        if (it < 2048) {
            // ---- f1 quarter: compacted bucket, zero wasted iterations ----
            int plane = it >> 2, q = it & 3;
            int b = plane >> 7, c = plane & 127;
            int cnt = g_cnt[q];
            const int4* ent = ((const int4*)g_f1b) + q * N_IDX;
            float* o = out + (size_t)(b * 960 + 64 + c) * N_IDX;
            int base = q << 12;                     // q*32*128
            for (int i = tid; i < cnt; i += 256) {
                int4 e = __ldg(ent + i);
                int sp = e.x - base;
                int dy = (e.y & 2) << 6;            // 0 or 128
                int dx = e.y & 1;
                int j  = e.y >> 4;
                float wy = __int_as_float(e.z), wx = __int_as_float(e.w);
                float v00 = s[sp];
                float v01 = s[sp + dx];
                float v10 = s[sp + dy];
                float v11 = s[sp + dy + dx];
                float tp = v00 + wx * (v01 - v00);
                float bt = v10 + wx * (v11 - v10);
                o[j] = tp + wy * (bt - tp);
            }
        } else if (it < 3072) {
            // ---- f2: one full plane, all 4096 j ----
            int p = it - 2048;
            int b = p >> 8, c = p & 255;
            const int4* meta = (const int4*)(g_meta + N_IDX);
            float* o = out + (size_t)(b * 960 + 192 + c) * N_IDX;
            for (int j = tid; j < N_IDX; j += 256) {
                int4 mr = __ldg(meta + j);
                int p00 = mr.x;
                int dy = mr.y >> 16, dx = mr.y & 0xffff;
                float wy = __int_as_float(mr.z), wx = __int_as_float(mr.w);
                float v00 = s[p00];
                float v01 = s[p00 + dx];
                float v10 = s[p00 + dy];
                float v11 = s[p00 + dy + dx];
                float tp = v00 + wx * (v01 - v00);
                float bt = v10 + wx * (v11 - v10);
                o[j] = tp + wy * (bt - tp);
            }
        } else if (it < 3584) {
            // ---- f3: 4 channels linear in smem; lane-quad channel split ----
            int g = it - 3072;
            int b = g >> 7, cg = g & 127;
            int c0 = cg * 4;
            const int4* meta = (const int4*)(g_meta + 2 * N_IDX);
            int cc = tid & 3;
            const float* sc = s + cc * 1024;
            float* o = out + (size_t)(b * 960 + 448 + c0 + cc) * N_IDX;
            for (int j = tid >> 2; j < N_IDX; j += 64) {
                int4 mr = __ldg(meta + j);          // 4 lanes share -> broadcast
                int p00 = mr.x;
                int dy = mr.y >> 16, dx = mr.y & 0xffff;
                float wy = __int_as_float(mr.z), wx = __int_as_float(mr.w);
                float v00 = sc[p00];
                float v01 = sc[p00 + dx];
                float v10 = sc[p00 + dy];
                float v11 = sc[p00 + dy + dx];
                float tp = v00 + wx * (v01 - v00);
                float bt = v10 + wx * (v11 - v10);
                o[j] = tp + wy * (bt - tp);
            }
        } else {
            // ---- f0: identity gather, half a plane per item (no copy) ----
            int r = it - 3584;
            int plane = r >> 1, half = r & 1;
            int b = plane >> 6, c = plane & 63;
            const float* pp = f0 + (size_t)plane * 65536;
            float* o = out + (size_t)(b * 960 + c) * N_IDX;
            int j0 = half << 11;
            #pragma unroll 4
            for (int j = j0 + tid; j < j0 + 2048; j += 256)
                o[j] = __ldg(pp + __ldg(indices + j));
        }
        __syncthreads();
    }
}

extern "C" void kernel_launch(void* const* d_in, const int* in_sizes, int n_in,
                              void* d_out, int out_size) {
    const float* f0 = nullptr; const float* f1 = nullptr;
    const float* f2 = nullptr; const float* f3 = nullptr;
    const int* indices = nullptr;
    for (int i = 0; i < n_in; i++) {
        switch (in_sizes[i]) {
            case 16777216: f0 = (const float*)d_in[i]; break;
            case 8388608:  f1 = (const float*)d_in[i]; break;
            case 4194304:  f2 = (const float*)d_in[i]; break;
            case 2097152:  f3 = (const float*)d_in[i]; break;
            case N_IDX:    indices = (const int*)d_in[i]; break;
        }
    }
    if (!f0 || !f1 || !f2 || !f3 || !indices) {
        f0 = (const float*)d_in[0];
        f1 = (const float*)d_in[1];
        f2 = (const float*)d_in[2];
        f3 = (const float*)d_in[3];
        indices = (const int*)d_in[4];
    }
    float* out = (float*)d_out;

    zero_cnt<<<1, 32>>>();
    precompute_meta<<<(3 * N_IDX + 255) / 256, 256>>>(indices);
    persist_gather<<<GRID_P, 256, DYN_SMEM>>>(f0, f1, f2, f3, indices, out);
}

// round 7
// speedup vs baseline: 1.4964x; 1.4964x over previous
#include <cuda_runtime.h>
#include <cstdint>

#define N_IDX 4096

struct __align__(16) Meta { int p00; int d; float wy; float wx; };
__device__ Meta g_meta[3 * N_IDX];

__global__ void precompute_meta(const int* __restrict__ indices) {
    int t = blockIdx.x * blockDim.x + threadIdx.x;
    if (t >= 3 * N_IDX) return;
    int lvl = t / N_IDX;        // 0 -> f1 (H=128), 1 -> f2 (64), 2 -> f3 (32)
    int j   = t - lvl * N_IDX;
    int H   = 128 >> lvl;
    float scale = (float)H * (1.0f / 256.0f);

    int idx = indices[j];
    int iy = idx >> 8;
    int ix = idx & 255;
    float sy = ((float)iy + 0.5f) * scale - 0.5f;
    float sx = ((float)ix + 0.5f) * scale - 0.5f;
    float y0f = floorf(sy), x0f = floorf(sx);
    float wy = sy - y0f,    wx = sx - x0f;
    int y0 = (int)y0f, x0 = (int)x0f;
    int y0c = min(max(y0,     0), H - 1);
    int y1c = min(max(y0 + 1, 0), H - 1);
    int x0c = min(max(x0,     0), H - 1);
    int x1c = min(max(x0 + 1, 0), H - 1);

    Meta m;
    m.p00 = y0c * H + x0c;
    m.d   = (((y1c - y0c) * H) << 16) | (x1c - x0c);
    m.wy  = wy;
    m.wx  = wx;
    g_meta[t] = m;
}

// CTA roles:
//   [0,1024)    : f1 — 512 planes x 2 row-halves (65/64 rows, 33.3KB smem)
//   [1024,1536) : f2 — 2 channels interleaved (float2 taps, 16KB)
//   [1536,1792) : f3 — 8 channels interleaved (2x float4 taps, 32KB)
//   [1792,2304) : f0 — identity LDG gather, half-plane per CTA
__global__ __launch_bounds__(256, 4) void fused_gather(
    const float* __restrict__ f0, const float* __restrict__ f1,
    const float* __restrict__ f2, const float* __restrict__ f3,
    const int*   __restrict__ indices, float* __restrict__ out)
{
    extern __shared__ float s[];
    int bid = blockIdx.x;
    int tid = threadIdx.x;

    if (bid < 1024) {
        // ---- f1 ----
        int plane = bid >> 1, half = bid & 1;
        int b = plane >> 7, c = plane & 127;
        int r0 = half << 6;
        int nrows = 65 - half;
        const float4* src4 =
            (const float4*)(f1 + (size_t)(b * 128 + c) * 16384 + r0 * 128);
        float4* s4 = (float4*)s;
        #pragma unroll 8
        for (int i = tid; i < nrows * 32; i += 256) s4[i] = src4[i];
        __syncthreads();

        const int4* meta = (const int4*)(g_meta);
        float* o = out + (size_t)(b * 960 + 64 + c) * N_IDX;
        int base = r0 << 7;
        // 16 j/thread, pipelined 4-wide
        #pragma unroll
        for (int blk = 0; blk < 4; blk++) {
            int j0 = blk * 1024 + tid;
            int4 mr[4];
            #pragma unroll
            for (int u = 0; u < 4; u++) mr[u] = __ldg(meta + j0 + u * 256);
            #pragma unroll
            for (int u = 0; u < 4; u++) {
                int p00 = mr[u].x;
                if (((p00 >> 13) & 1) == half) {
                    int sp = p00 - base;
                    int dy = mr[u].y >> 16, dx = mr[u].y & 0xffff;
                    float wy = __int_as_float(mr[u].z), wx = __int_as_float(mr[u].w);
                    float v00 = s[sp];
                    float v01 = s[sp + dx];
                    float v10 = s[sp + dy];
                    float v11 = s[sp + dy + dx];
                    float tp = v00 + wx * (v01 - v00);
                    float bt = v10 + wx * (v11 - v10);
                    o[j0 + u * 256] = tp + wy * (bt - tp);
                }
            }
        }
    } else if (bid < 1536) {
        // ---- f2: s[2p + cc] ----
        int rel = bid - 1024;
        int b = rel >> 7, cg = rel & 127;
        int c0 = cg * 2;
        const float4* p0 = (const float4*)(f2 + (size_t)(b * 256 + c0) * 4096);
        const float4* p1 = (const float4*)(f2 + (size_t)(b * 256 + c0 + 1) * 4096);
        float4* s4 = (float4*)s;
        #pragma unroll 4
        for (int i = tid; i < 1024; i += 256) {
            float4 a = __ldg(p0 + i), bb = __ldg(p1 + i);
            s4[2 * i]     = make_float4(a.x, bb.x, a.y, bb.y);
            s4[2 * i + 1] = make_float4(a.z, bb.z, a.w, bb.w);
        }
        __syncthreads();

        const int4* meta = (const int4*)(g_meta + N_IDX);
        float* o = out + (size_t)(b * 960 + 192 + c0) * N_IDX;
        #pragma unroll
        for (int blk = 0; blk < 4; blk++) {
            int j0 = blk * 1024 + tid;
            int4 mr[4];
            #pragma unroll
            for (int u = 0; u < 4; u++) mr[u] = __ldg(meta + j0 + u * 256);
            #pragma unroll
            for (int u = 0; u < 4; u++) {
                int p00 = mr[u].x;
                int dy = mr[u].y >> 16, dx = mr[u].y & 0xffff;
                float wy = __int_as_float(mr[u].z), wx = __int_as_float(mr[u].w);
                float2 v00 = *(const float2*)(s + 2 * p00);
                float2 v01 = *(const float2*)(s + 2 * (p00 + dx));
                float2 v10 = *(const float2*)(s + 2 * (p00 + dy));
                float2 v11 = *(const float2*)(s + 2 * (p00 + dy + dx));
                float t0 = v00.x + wx * (v01.x - v00.x);
                float b0 = v10.x + wx * (v11.x - v10.x);
                o[j0 + u * 256] = t0 + wy * (b0 - t0);
                float t1 = v00.y + wx * (v01.y - v00.y);
                float b1 = v10.y + wx * (v11.y - v10.y);
                o[N_IDX + j0 + u * 256] = t1 + wy * (b1 - t1);
            }
        }
    } else if (bid < 1792) {
        // ---- f3: s4[2p], s4[2p+1] = 8 channels of pixel p ----
        int rel = bid - 1536;
        int b = rel >> 6, cg = rel & 63;
        int c0 = cg * 8;
        const float* src = f3 + (size_t)(b * 512 + c0) * 1024;
        float4* s4 = (float4*)s;
        #pragma unroll 2
        for (int p = tid; p < 1024; p += 256) {
            float4 a, q;
            a.x = __ldg(src +    0 + p); a.y = __ldg(src + 1024 + p);
            a.z = __ldg(src + 2048 + p); a.w = __ldg(src + 3072 + p);
            q.x = __ldg(src + 4096 + p); q.y = __ldg(src + 5120 + p);
            q.z = __ldg(src + 6144 + p); q.w = __ldg(src + 7168 + p);
            s4[p * 2]     = a;
            s4[p * 2 + 1] = q;
        }
        __syncthreads();

        const int4* meta = (const int4*)(g_meta + 2 * N_IDX);
        float* o = out + (size_t)(b * 960 + 448 + c0) * N_IDX;
        #pragma unroll
        for (int blk = 0; blk < 8; blk++) {
            int j0 = blk * 512 + tid;
            int4 mr[2];
            mr[0] = __ldg(meta + j0);
            mr[1] = __ldg(meta + j0 + 256);
            #pragma unroll
            for (int u = 0; u < 2; u++) {
                int p00 = mr[u].x;
                int dy = mr[u].y >> 16, dx = mr[u].y & 0xffff;
                float wy = __int_as_float(mr[u].z), wx = __int_as_float(mr[u].w);
                int i00 = 2 * p00, i01 = 2 * (p00 + dx);
                int i10 = 2 * (p00 + dy), i11 = 2 * (p00 + dy + dx);
                float4 a00 = s4[i00], b00 = s4[i00 + 1];
                float4 a01 = s4[i01], b01 = s4[i01 + 1];
                float4 a10 = s4[i10], b10 = s4[i10 + 1];
                float4 a11 = s4[i11], b11 = s4[i11 + 1];
                int j = j0 + u * 256;
                #define LERP2(v00v, v01v, v10v, v11v, cc)                     \
                    { float tp = v00v + wx * (v01v - v00v);                   \
                      float bt = v10v + wx * (v11v - v10v);                   \
                      o[(cc) * N_IDX + j] = tp + wy * (bt - tp); }
                LERP2(a00.x, a01.x, a10.x, a11.x, 0)
                LERP2(a00.y, a01.y, a10.y, a11.y, 1)
                LERP2(a00.z, a01.z, a10.z, a11.z, 2)
                LERP2(a00.w, a01.w, a10.w, a11.w, 3)
                LERP2(b00.x, b01.x, b10.x, b11.x, 4)
                LERP2(b00.y, b01.y, b10.y, b11.y, 5)
                LERP2(b00.z, b01.z, b10.z, b11.z, 6)
                LERP2(b00.w, b01.w, b10.w, b11.w, 7)
                #undef LERP2
            }
        }
    } else {
        // ---- f0: identity gather, deep MLP ----
        int rel = bid - 1792;
        int plane = rel >> 1, half = rel & 1;
        int b = plane >> 6, c = plane & 63;
        const float* pp = f0 + (size_t)plane * 65536;
        float* o = out + (size_t)(b * 960 + c) * N_IDX;
        int j0 = half << 11;
        int idx8[8];
        #pragma unroll
        for (int u = 0; u < 8; u++) idx8[u] = __ldg(indices + j0 + tid + u * 256);
        float v8[8];
        #pragma unroll
        for (int u = 0; u < 8; u++) v8[u] = __ldg(pp + idx8[u]);
        #pragma unroll
        for (int u = 0; u < 8; u++) o[j0 + tid + u * 256] = v8[u];
    }
}

extern "C" void kernel_launch(void* const* d_in, const int* in_sizes, int n_in,
                              void* d_out, int out_size) {
    const float* f0 = nullptr; const float* f1 = nullptr;
    const float* f2 = nullptr; const float* f3 = nullptr;
    const int* indices = nullptr;
    for (int i = 0; i < n_in; i++) {
        switch (in_sizes[i]) {
            case 16777216: f0 = (const float*)d_in[i]; break;
            case 8388608:  f1 = (const float*)d_in[i]; break;
            case 4194304:  f2 = (const float*)d_in[i]; break;
            case 2097152:  f3 = (const float*)d_in[i]; break;
            case N_IDX:    indices = (const int*)d_in[i]; break;
        }
    }
    if (!f0 || !f1 || !f2 || !f3 || !indices) {
        f0 = (const float*)d_in[0];
        f1 = (const float*)d_in[1];
        f2 = (const float*)d_in[2];
        f3 = (const float*)d_in[3];
        indices = (const int*)d_in[4];
    }
    float* out = (float*)d_out;

    precompute_meta<<<(3 * N_IDX + 255) / 256, 256>>>(indices);
    // 65 rows * 128 cols * 4B = 33280 B dynamic smem.
    fused_gather<<<2304, 256, 33280>>>(f0, f1, f2, f3, indices, out);
}